// round 3
// baseline (speedup 1.0000x reference)
#include <cuda_runtime.h>

#define N_NODES 20000
#define N_EDGES 640000
#define D 128

// ---- scratch (no allocations allowed). .bss zero-init on load; kernels
// self-reset g_deg/g_cursor each invocation so replays are deterministic. ----
__device__ int   g_deg[N_NODES];          // zeroed by scan kernel after use
__device__ int   g_cursor[N_NODES];       // zeroed by scan kernel before fill
__device__ int   g_rowstart[N_NODES + 1];
__device__ int   g_csr[N_EDGES];
__device__ float g_x[N_NODES * D];        // h + agg  (GEMM input)
__device__ float g_h[N_NODES * D];        // node features between layers

// ---------------------------------------------------------------------------
__global__ void count_deg_kernel(const int* __restrict__ ei) {
    int e = blockIdx.x * blockDim.x + threadIdx.x;
    if (e < N_EDGES) atomicAdd(&g_deg[ei[N_EDGES + e]], 1);
}

__global__ void scan_deg_kernel() {
    __shared__ int partial[1024];
    const int tid = threadIdx.x;
    const int CH  = (N_NODES + 1023) / 1024;   // 20
    const int base = tid * CH;

    int s = 0;
    for (int j = 0; j < CH; j++) {
        int idx = base + j;
        if (idx < N_NODES) s += g_deg[idx];
    }
    partial[tid] = s;
    __syncthreads();

    for (int off = 1; off < 1024; off <<= 1) {
        int v = 0;
        if (tid >= off) v = partial[tid - off];
        __syncthreads();
        if (tid >= off) partial[tid] += v;
        __syncthreads();
    }

    int run = (tid > 0) ? partial[tid - 1] : 0;
    for (int j = 0; j < CH; j++) {
        int idx = base + j;
        if (idx < N_NODES) {
            g_rowstart[idx] = run;
            run += g_deg[idx];
            g_deg[idx]    = 0;   // reset for next invocation
            g_cursor[idx] = 0;   // reset for fill phase
        }
    }
    if (tid == 1023) g_rowstart[N_NODES] = partial[1023];
}

__global__ void fill_csr_kernel(const int* __restrict__ ei) {
    int e = blockIdx.x * blockDim.x + threadIdx.x;
    if (e < N_EDGES) {
        int s = ei[e];
        int d = ei[N_EDGES + e];
        int pos = atomicAdd(&g_cursor[d], 1);
        g_csr[g_rowstart[d] + pos] = s;
    }
}

// ---------------------------------------------------------------------------
// aggregation: one WARP per node, lane owns 4 columns (float4).
__global__ __launch_bounds__(256) void aggregate_kernel(const float* __restrict__ hin) {
    const int lane = threadIdx.x & 31;
    const int node = blockIdx.x * 8 + (threadIdx.x >> 5);
    const int beg = g_rowstart[node];
    const int end = g_rowstart[node + 1];

    const float4* __restrict__ hv = (const float4*)hin;

    float4 a = hv[node * 32 + lane];
    float acc0 = a.x, acc1 = a.y, acc2 = a.z, acc3 = a.w;

    for (int k = beg; k < end; k += 8) {
        int kk = k + (lane & 7);
        int myj = (kk < end) ? g_csr[kk] : -1;
#pragma unroll
        for (int e = 0; e < 8; e++) {
            int j = __shfl_sync(0xffffffffu, myj, e);
            if (j >= 0) {
                float4 v = hv[j * 32 + lane];
                acc0 += v.x; acc1 += v.y; acc2 += v.z; acc3 += v.w;
            }
        }
    }
    float4 o; o.x = acc0; o.y = acc1; o.z = acc2; o.w = acc3;
    ((float4*)g_x)[node * 32 + lane] = o;
}

// ---------------------------------------------------------------------------
// Y[0:nrows, 0:128] = g_x @ W + b
// 128x128 tile per block, 256 threads, per-thread 8x8 accumulators.
// __launch_bounds__(256, 1): full 256-reg budget -> NO spills (the (256,2)
// variant capped at 128 regs and spilled accumulators into local memory).
__global__ __launch_bounds__(256, 1) void gemm_kernel(
    const float* __restrict__ W,
    const float* __restrict__ bias,
    float* __restrict__ Y,
    int nrows)
{
    __shared__ float Xs[128][36];   // 18 KB, row stride 36 (float4-aligned, conflict-free)
    __shared__ float Ws[32][128];   // 16 KB

    const int tid  = threadIdx.x;
    const int row0 = blockIdx.x * 128;
    const int ty   = tid >> 4;          // 0..15
    const int tx   = tid & 15;          // 0..15
    const int rbase = ty * 8;
    const int cbase = tx * 8;

    float acc[8][8];
#pragma unroll
    for (int r = 0; r < 8; r++)
#pragma unroll
        for (int c = 0; c < 8; c++) acc[r][c] = 0.f;

#pragma unroll
    for (int k0 = 0; k0 < 128; k0 += 32) {
        // load X tile: 128 rows x 32 k
        {
            int r  = tid >> 3;            // 0..31
            int kc = (tid & 7) * 4;       // 0..28
#pragma unroll
            for (int rr = 0; rr < 128; rr += 32) {
                int row = row0 + r + rr;
                float4 v = make_float4(0.f, 0.f, 0.f, 0.f);
                if (row < nrows) v = *(const float4*)&g_x[(long)row * D + k0 + kc];
                *(float4*)&Xs[r + rr][kc] = v;
            }
        }
        // load W tile: 32 k x 128 cols
#pragma unroll
        for (int i = 0; i < 4; i++) {
            int idx = tid + i * 256;
            int k   = idx >> 5;
            int c4  = (idx & 31) * 4;
            *(float4*)&Ws[k][c4] = __ldg((const float4*)&W[(k0 + k) * 128 + c4]);
        }
        __syncthreads();

#pragma unroll
        for (int k = 0; k < 32; k += 4) {
            float4 xf[8];
#pragma unroll
            for (int r = 0; r < 8; r++) xf[r] = *(const float4*)&Xs[rbase + r][k];
#pragma unroll
            for (int kk = 0; kk < 4; kk++) {
                float4 w0 = *(const float4*)&Ws[k + kk][cbase];
                float4 w1 = *(const float4*)&Ws[k + kk][cbase + 4];
#pragma unroll
                for (int r = 0; r < 8; r++) {
                    float xv = (kk == 0) ? xf[r].x : (kk == 1) ? xf[r].y
                             : (kk == 2) ? xf[r].z : xf[r].w;
                    acc[r][0] += xv * w0.x;
                    acc[r][1] += xv * w0.y;
                    acc[r][2] += xv * w0.z;
                    acc[r][3] += xv * w0.w;
                    acc[r][4] += xv * w1.x;
                    acc[r][5] += xv * w1.y;
                    acc[r][6] += xv * w1.z;
                    acc[r][7] += xv * w1.w;
                }
            }
        }
        __syncthreads();
    }

    float4 b0 = *(const float4*)&bias[cbase];
    float4 b1 = *(const float4*)&bias[cbase + 4];
#pragma unroll
    for (int r = 0; r < 8; r++) {
        int row = row0 + rbase + r;
        if (row < nrows) {
            float4 o0, o1;
            o0.x = acc[r][0] + b0.x; o0.y = acc[r][1] + b0.y;
            o0.z = acc[r][2] + b0.z; o0.w = acc[r][3] + b0.w;
            o1.x = acc[r][4] + b1.x; o1.y = acc[r][5] + b1.y;
            o1.z = acc[r][6] + b1.z; o1.w = acc[r][7] + b1.w;
            *(float4*)&Y[(long)row * D + cbase]     = o0;
            *(float4*)&Y[(long)row * D + cbase + 4] = o1;
        }
    }
}

// ---------------------------------------------------------------------------
extern "C" void kernel_launch(void* const* d_in, const int* in_sizes, int n_in,
                              void* d_out, int out_size) {
    const float* h  = (const float*)d_in[0];
    const int*   ei = (const int*)d_in[1];
    const float* Wt[4] = { (const float*)d_in[2], (const float*)d_in[4],
                           (const float*)d_in[6], (const float*)d_in[8] };
    const float* bt[4] = { (const float*)d_in[3], (const float*)d_in[5],
                           (const float*)d_in[7], (const float*)d_in[9] };
    float* out = (float*)d_out;

    count_deg_kernel<<<(N_EDGES + 255) / 256, 256>>>(ei);
    scan_deg_kernel<<<1, 1024>>>();
    fill_csr_kernel<<<(N_EDGES + 255) / 256, 256>>>(ei);

    const int agg_blocks  = N_NODES / 8;              // 2500
    const int gemm_blocks = (N_NODES + 127) / 128;    // 157

    aggregate_kernel<<<agg_blocks, 256>>>(h);
    gemm_kernel<<<gemm_blocks, 256>>>(Wt[0], bt[0], g_h, N_NODES);

    aggregate_kernel<<<agg_blocks, 256>>>(g_h);
    gemm_kernel<<<gemm_blocks, 256>>>(Wt[1], bt[1], g_h, N_NODES);

    aggregate_kernel<<<agg_blocks, 256>>>(g_h);
    gemm_kernel<<<gemm_blocks, 256>>>(Wt[2], bt[2], g_h, N_NODES);

    aggregate_kernel<<<agg_blocks, 256>>>(g_h);
    gemm_kernel<<<gemm_blocks, 256>>>(Wt[3], bt[3], out, N_NODES);
}

// round 5
// speedup vs baseline: 1.0218x; 1.0218x over previous
#include <cuda_runtime.h>

#define N_NODES 20000
#define N_EDGES 640000
#define D 128

// ---- scratch (no allocations). .bss zero-init; scan kernel self-resets
// g_deg/g_cursor each invocation so graph replays are deterministic. ----
__device__ int   g_deg[N_NODES];
__device__ int   g_cursor[N_NODES];
__device__ int   g_rowstart[N_NODES + 1];
__device__ int   g_csr[N_EDGES];
__device__ float g_hA[N_NODES * D];   // ping
__device__ float g_hB[N_NODES * D];   // pong

// ---------------------------------------------------------------------------
__global__ void count_deg_kernel(const int* __restrict__ ei) {
    int e = blockIdx.x * blockDim.x + threadIdx.x;
    if (e < N_EDGES) atomicAdd(&g_deg[ei[N_EDGES + e]], 1);
}

__global__ void scan_deg_kernel() {
    __shared__ int partial[1024];
    const int tid = threadIdx.x;
    const int CH  = (N_NODES + 1023) / 1024;   // 20
    const int base = tid * CH;

    int s = 0;
#pragma unroll
    for (int j = 0; j < CH; j++) {
        int idx = base + j;
        if (idx < N_NODES) s += g_deg[idx];
    }
    partial[tid] = s;
    __syncthreads();

    for (int off = 1; off < 1024; off <<= 1) {
        int v = 0;
        if (tid >= off) v = partial[tid - off];
        __syncthreads();
        if (tid >= off) partial[tid] += v;
        __syncthreads();
    }

    int run = (tid > 0) ? partial[tid - 1] : 0;
#pragma unroll
    for (int j = 0; j < CH; j++) {
        int idx = base + j;
        if (idx < N_NODES) {
            g_rowstart[idx] = run;
            run += g_deg[idx];
            g_deg[idx]    = 0;   // reset for next replay
            g_cursor[idx] = 0;   // reset for fill phase
        }
    }
    if (tid == 1023) g_rowstart[N_NODES] = partial[1023];
}

__global__ void fill_csr_kernel(const int* __restrict__ ei) {
    int e = blockIdx.x * blockDim.x + threadIdx.x;
    if (e < N_EDGES) {
        int s = ei[e];
        int d = ei[N_EDGES + e];
        int pos = atomicAdd(&g_cursor[d], 1);
        g_csr[g_rowstart[d] + pos] = s;
    }
}

// ---------------------------------------------------------------------------
// Fused layer: per block, aggregate 64 nodes into smem, then GEMM x W + b.
// hin and hout MUST be distinct arrays (Phase A reads arbitrary rows of hin
// while other blocks write hout).
__global__ __launch_bounds__(256) void fused_layer_kernel(
    const float* __restrict__ hin,
    const float* __restrict__ W,
    const float* __restrict__ bias,
    float* __restrict__ hout,
    int nrows)
{
    __shared__ float Xs[64][128];   // 32 KB  (aggregated rows, full K)
    __shared__ float Ws[32][128];   // 16 KB  (W k-tile)

    const int tid  = threadIdx.x;
    const int lane = tid & 31;
    const int wid  = tid >> 5;
    const int row0 = blockIdx.x * 64;
    const float4* __restrict__ hv = (const float4*)hin;

    // ---- Phase A: aggregation into Xs (one warp per node, 8 nodes/warp) ----
#pragma unroll
    for (int n = wid; n < 64; n += 8) {
        int node = row0 + n;
        float4 a = make_float4(0.f, 0.f, 0.f, 0.f);
        if (node < nrows) {
            a = hv[node * 32 + lane];
            int beg = g_rowstart[node];
            int end = g_rowstart[node + 1];
            for (int k = beg; k < end; k += 8) {
                int kk = k + (lane & 7);
                int myj = (kk < end) ? g_csr[kk] : -1;
#pragma unroll
                for (int e = 0; e < 8; e++) {
                    int j = __shfl_sync(0xffffffffu, myj, e);
                    if (j >= 0) {
                        float4 v = hv[j * 32 + lane];
                        a.x += v.x; a.y += v.y; a.z += v.z; a.w += v.w;
                    }
                }
            }
        }
        *(float4*)&Xs[n][lane * 4] = a;
    }
    __syncthreads();

    // ---- Phase B: hout[row0:row0+64, :] = Xs @ W + b ----
    const int ty = tid >> 4;            // 0..15
    const int tx = tid & 15;            // 0..15
    const int rbase = ty * 4;           // 0..60
    const int cbase = tx * 8;           // 0..120

    float acc[4][8];
#pragma unroll
    for (int r = 0; r < 4; r++)
#pragma unroll
        for (int c = 0; c < 8; c++) acc[r][c] = 0.f;

#pragma unroll
    for (int k0 = 0; k0 < 128; k0 += 32) {
        // load W k-tile: 32 x 128 (1024 float4 / 256 threads = 4 each)
#pragma unroll
        for (int i = 0; i < 4; i++) {
            int idx = tid + i * 256;
            int k   = idx >> 5;
            int c4  = (idx & 31) * 4;
            *(float4*)&Ws[k][c4] = __ldg((const float4*)&W[(k0 + k) * 128 + c4]);
        }
        __syncthreads();

#pragma unroll
        for (int k = 0; k < 32; k += 4) {
            float4 xf[4];
#pragma unroll
            for (int r = 0; r < 4; r++)
                xf[r] = *(const float4*)&Xs[rbase + r][k0 + k];
#pragma unroll
            for (int kk = 0; kk < 4; kk++) {
                float4 w0 = *(const float4*)&Ws[k + kk][cbase];
                float4 w1 = *(const float4*)&Ws[k + kk][cbase + 4];
#pragma unroll
                for (int r = 0; r < 4; r++) {
                    float xv = (kk == 0) ? xf[r].x : (kk == 1) ? xf[r].y
                             : (kk == 2) ? xf[r].z : xf[r].w;
                    acc[r][0] += xv * w0.x;
                    acc[r][1] += xv * w0.y;
                    acc[r][2] += xv * w0.z;
                    acc[r][3] += xv * w0.w;
                    acc[r][4] += xv * w1.x;
                    acc[r][5] += xv * w1.y;
                    acc[r][6] += xv * w1.z;
                    acc[r][7] += xv * w1.w;
                }
            }
        }
        __syncthreads();
    }

    float4 b0 = *(const float4*)&bias[cbase];
    float4 b1 = *(const float4*)&bias[cbase + 4];
#pragma unroll
    for (int r = 0; r < 4; r++) {
        int row = row0 + rbase + r;
        if (row < nrows) {
            float4 o0, o1;
            o0.x = acc[r][0] + b0.x; o0.y = acc[r][1] + b0.y;
            o0.z = acc[r][2] + b0.z; o0.w = acc[r][3] + b0.w;
            o1.x = acc[r][4] + b1.x; o1.y = acc[r][5] + b1.y;
            o1.z = acc[r][6] + b1.z; o1.w = acc[r][7] + b1.w;
            *(float4*)&hout[(long)row * D + cbase]     = o0;
            *(float4*)&hout[(long)row * D + cbase + 4] = o1;
        }
    }
}

// ---------------------------------------------------------------------------
extern "C" void kernel_launch(void* const* d_in, const int* in_sizes, int n_in,
                              void* d_out, int out_size) {
    const float* h  = (const float*)d_in[0];
    const int*   ei = (const int*)d_in[1];
    const float* Wt[4] = { (const float*)d_in[2], (const float*)d_in[4],
                           (const float*)d_in[6], (const float*)d_in[8] };
    const float* bt[4] = { (const float*)d_in[3], (const float*)d_in[5],
                           (const float*)d_in[7], (const float*)d_in[9] };
    float* out = (float*)d_out;

    // CSR build: exactly 3 kernels so my 4th launch (= global slot 5,
    // the ncu-profiled one) is fused layer 0.
    count_deg_kernel<<<(N_EDGES + 255) / 256, 256>>>(ei);
    scan_deg_kernel<<<1, 1024>>>();
    fill_csr_kernel<<<(N_EDGES + 255) / 256, 256>>>(ei);

    const int blocks = (N_NODES + 63) / 64;   // 313

    // ping-pong: never read and write the same buffer within one launch
    fused_layer_kernel<<<blocks, 256>>>(h,    Wt[0], bt[0], g_hA, N_NODES);
    fused_layer_kernel<<<blocks, 256>>>(g_hA, Wt[1], bt[1], g_hB, N_NODES);
    fused_layer_kernel<<<blocks, 256>>>(g_hB, Wt[2], bt[2], g_hA, N_NODES);
    fused_layer_kernel<<<blocks, 256>>>(g_hA, Wt[3], bt[3], out,  N_NODES);
}

// round 6
// speedup vs baseline: 10.1022x; 9.8863x over previous
#include <cuda_runtime.h>

#define N_NODES 20000
#define N_EDGES 640000
#define D 128
#define NBLK 148          // 1 block/SM -> co-residency guaranteed (no barrier deadlock)
#define NTHR 256

// ---- scratch (no allocations). .bss zero-init. Barrier state and deg/cursor
// return to 0 at kernel end, so graph replays are deterministic. ----
__device__ int      g_deg[N_NODES];
__device__ int      g_cursor[N_NODES];
__device__ int      g_rowstart[N_NODES + 1];
__device__ int      g_csr[N_EDGES];
__device__ float    g_h0[N_NODES * D];
__device__ float    g_h1[N_NODES * D];
__device__ float    g_h2[N_NODES * D];
__device__ unsigned g_bar_count;   // 0 at start and end
__device__ unsigned g_bar_sense;   // 0 at start; 6 toggles per run -> ends 0

// sense-reversing grid barrier; all NBLK blocks are co-resident (1/SM).
__device__ __forceinline__ void grid_barrier(unsigned& sense) {
    __syncthreads();
    sense ^= 1u;                       // every thread tracks; only tid 0 uses
    if (threadIdx.x == 0) {
        __threadfence();               // release: publish this block's writes
        unsigned arrived = atomicAdd(&g_bar_count, 1u);
        if (arrived == NBLK - 1) {
            g_bar_count = 0;
            __threadfence();
            atomicExch(&g_bar_sense, sense);
        } else {
            while (atomicAdd(&g_bar_sense, 0u) != sense) __nanosleep(64);
        }
    }
    __syncthreads();
}

// ---------------------------------------------------------------------------
struct SMem {
    float Xs[64][128];   // 32 KB : aggregated rows
    float Ws[32][128];   // 16 KB : W k-tile (reused as scan scratch)
};

// one fused layer: aggregate 64-node tiles into smem, GEMM x W + b.
// hin != hout; every scratch buffer is written exactly once and read exactly
// once per launch (no stale-L1 hazard across SMs).
__device__ __forceinline__ void do_layer(
    SMem& sm,
    const float* __restrict__ hin,
    const float* __restrict__ W,
    const float* __restrict__ bias,
    float* __restrict__ hout)
{
    const int tid  = threadIdx.x;
    const int lane = tid & 31;
    const int wid  = tid >> 5;
    const float4* __restrict__ hv = (const float4*)hin;

    const int ty = tid >> 4, tx = tid & 15;
    const int rbase = ty * 4, cbase = tx * 8;

    for (int tile = blockIdx.x; tile * 64 < N_NODES; tile += NBLK) {
        const int row0 = tile * 64;

        // ---- Phase A: aggregation (one warp per node, 8 nodes/warp) ----
#pragma unroll
        for (int n = wid; n < 64; n += 8) {
            int node = row0 + n;
            float4 a = make_float4(0.f, 0.f, 0.f, 0.f);
            if (node < N_NODES) {
                a = hv[node * 32 + lane];
                int beg = g_rowstart[node];
                int end = g_rowstart[node + 1];
                for (int k = beg; k < end; k += 8) {
                    int kk = k + (lane & 7);
                    int myj = (kk < end) ? g_csr[kk] : -1;
#pragma unroll
                    for (int e = 0; e < 8; e++) {
                        int j = __shfl_sync(0xffffffffu, myj, e);
                        if (j >= 0) {
                            float4 v = hv[j * 32 + lane];
                            a.x += v.x; a.y += v.y; a.z += v.z; a.w += v.w;
                        }
                    }
                }
            }
            *(float4*)&sm.Xs[n][lane * 4] = a;
        }
        __syncthreads();

        // ---- Phase B: hout[row0:row0+64, :] = Xs @ W + b ----
        float acc[4][8];
#pragma unroll
        for (int r = 0; r < 4; r++)
#pragma unroll
            for (int c = 0; c < 8; c++) acc[r][c] = 0.f;

#pragma unroll
        for (int k0 = 0; k0 < 128; k0 += 32) {
#pragma unroll
            for (int i = 0; i < 4; i++) {
                int idx = tid + i * 256;
                int k   = idx >> 5;
                int c4  = (idx & 31) * 4;
                *(float4*)&sm.Ws[k][c4] =
                    __ldg((const float4*)&W[(k0 + k) * 128 + c4]);
            }
            __syncthreads();

#pragma unroll
            for (int k = 0; k < 32; k += 4) {
                float4 xf[4];
#pragma unroll
                for (int r = 0; r < 4; r++)
                    xf[r] = *(const float4*)&sm.Xs[rbase + r][k0 + k];
#pragma unroll
                for (int kk = 0; kk < 4; kk++) {
                    float4 w0 = *(const float4*)&sm.Ws[k + kk][cbase];
                    float4 w1 = *(const float4*)&sm.Ws[k + kk][cbase + 4];
#pragma unroll
                    for (int r = 0; r < 4; r++) {
                        float xv = (kk == 0) ? xf[r].x : (kk == 1) ? xf[r].y
                                 : (kk == 2) ? xf[r].z : xf[r].w;
                        acc[r][0] += xv * w0.x; acc[r][1] += xv * w0.y;
                        acc[r][2] += xv * w0.z; acc[r][3] += xv * w0.w;
                        acc[r][4] += xv * w1.x; acc[r][5] += xv * w1.y;
                        acc[r][6] += xv * w1.z; acc[r][7] += xv * w1.w;
                    }
                }
            }
            __syncthreads();
        }

        float4 b0 = *(const float4*)&bias[cbase];
        float4 b1 = *(const float4*)&bias[cbase + 4];
#pragma unroll
        for (int r = 0; r < 4; r++) {
            int row = row0 + rbase + r;
            if (row < N_NODES) {
                float4 o0, o1;
                o0.x = acc[r][0] + b0.x; o0.y = acc[r][1] + b0.y;
                o0.z = acc[r][2] + b0.z; o0.w = acc[r][3] + b0.w;
                o1.x = acc[r][4] + b1.x; o1.y = acc[r][5] + b1.y;
                o1.z = acc[r][6] + b1.z; o1.w = acc[r][7] + b1.w;
                *(float4*)&hout[(long)row * D + cbase]     = o0;
                *(float4*)&hout[(long)row * D + cbase + 4] = o1;
            }
        }
        // acc in regs only; next tile's Phase A rewrites Xs after this sync
        __syncthreads();
    }
}

// ---------------------------------------------------------------------------
__global__ __launch_bounds__(NTHR) void gin_persistent_kernel(
    const float* __restrict__ h,
    const int*   __restrict__ ei,
    const float* __restrict__ W0, const float* __restrict__ b0,
    const float* __restrict__ W1, const float* __restrict__ b1,
    const float* __restrict__ W2, const float* __restrict__ b2,
    const float* __restrict__ W3, const float* __restrict__ b3,
    float* __restrict__ out)
{
    __shared__ SMem sm;
    const int tid = threadIdx.x;
    unsigned sense = 0;

    // ---- Phase 1: count in-degrees (g_deg is 0 on entry) ----
    for (int e = blockIdx.x * NTHR + tid; e < N_EDGES; e += NBLK * NTHR)
        atomicAdd(&g_deg[ei[N_EDGES + e]], 1);
    grid_barrier(sense);                                   // b1

    // ---- Phase 2: exclusive scan (block 0 only), reset deg/cursor ----
    if (blockIdx.x == 0) {
        int* partial = (int*)sm.Ws;     // reuse smem (1 KB of 16 KB)
        const int CH = (N_NODES + NTHR - 1) / NTHR;        // 79
        const int base = tid * CH;

        int s = 0;
        for (int j = 0; j < CH; j++) {
            int idx = base + j;
            if (idx < N_NODES) s += g_deg[idx];
        }
        partial[tid] = s;
        __syncthreads();
        for (int off = 1; off < NTHR; off <<= 1) {
            int v = 0;
            if (tid >= off) v = partial[tid - off];
            __syncthreads();
            if (tid >= off) partial[tid] += v;
            __syncthreads();
        }
        int run = (tid > 0) ? partial[tid - 1] : 0;
        for (int j = 0; j < CH; j++) {
            int idx = base + j;
            if (idx < N_NODES) {
                g_rowstart[idx] = run;
                run += g_deg[idx];
                g_deg[idx]    = 0;     // reset for next replay
                g_cursor[idx] = 0;     // reset for fill phase
            }
        }
        if (tid == NTHR - 1) g_rowstart[N_NODES] = partial[NTHR - 1];
        __syncthreads();
    }
    grid_barrier(sense);                                   // b2

    // ---- Phase 3: fill CSR ----
    for (int e = blockIdx.x * NTHR + tid; e < N_EDGES; e += NBLK * NTHR) {
        int s = ei[e];
        int d = ei[N_EDGES + e];
        int pos = atomicAdd(&g_cursor[d], 1);
        g_csr[g_rowstart[d] + pos] = s;
    }
    grid_barrier(sense);                                   // b3

    // ---- Phases 4-7: the four GIN layers ----
    do_layer(sm, h,    W0, b0, g_h0);
    grid_barrier(sense);                                   // b4
    do_layer(sm, g_h0, W1, b1, g_h1);
    grid_barrier(sense);                                   // b5
    do_layer(sm, g_h1, W2, b2, g_h2);
    grid_barrier(sense);                                   // b6  (even count -> sense ends 0)
    do_layer(sm, g_h2, W3, b3, out);
}

// ---------------------------------------------------------------------------
extern "C" void kernel_launch(void* const* d_in, const int* in_sizes, int n_in,
                              void* d_out, int out_size) {
    const float* h  = (const float*)d_in[0];
    const int*   ei = (const int*)d_in[1];

    gin_persistent_kernel<<<NBLK, NTHR>>>(
        h, ei,
        (const float*)d_in[2], (const float*)d_in[3],
        (const float*)d_in[4], (const float*)d_in[5],
        (const float*)d_in[6], (const float*)d_in[7],
        (const float*)d_in[8], (const float*)d_in[9],
        (float*)d_out);
}

// round 7
// speedup vs baseline: 14.9616x; 1.4810x over previous
#include <cuda_runtime.h>

#define N_NODES 20000
#define N_EDGES 640000
#define D 128
#define NBLK 148          // 1 block/SM -> co-residency guaranteed for grid barrier
#define NTHR 512

// ---- scratch (no allocations). .bss zero-init. Barrier state and deg/cursor
// return to 0 at kernel end, so graph replays are deterministic. ----
__device__ int      g_deg[N_NODES];
__device__ int      g_cursor[N_NODES];
__device__ int      g_rowstart[N_NODES + 1];
__device__ int      g_csr[N_EDGES];
__device__ float    g_h0[N_NODES * D];
__device__ float    g_h1[N_NODES * D];
__device__ float    g_h2[N_NODES * D];
__device__ unsigned g_bar_count;   // 0 at start and end
__device__ unsigned g_bar_sense;   // 0 at start; 6 toggles per run -> ends 0

struct SMem {
    float Xs[64][128];    // 32 KB : aggregated rows for current tile
    float Wf[128][128];   // 64 KB : full W, resident for the whole layer
};

// sense-reversing grid barrier; all NBLK blocks are co-resident (1/SM).
__device__ __forceinline__ void grid_barrier(unsigned& sense) {
    __syncthreads();
    sense ^= 1u;
    if (threadIdx.x == 0) {
        __threadfence();
        unsigned arrived = atomicAdd(&g_bar_count, 1u);
        if (arrived == NBLK - 1) {
            g_bar_count = 0;
            __threadfence();
            atomicExch(&g_bar_sense, sense);
        } else {
            while (atomicAdd(&g_bar_sense, 0u) != sense) __nanosleep(64);
        }
    }
    __syncthreads();
}

// ---------------------------------------------------------------------------
// one fused layer. hin != hout. W is loaded into smem ONCE, then the tile
// loop runs aggregation (Phase A) + GEMM (Phase B) with only 2 syncs/tile.
__device__ __forceinline__ void do_layer(
    SMem& sm,
    const float* __restrict__ hin,
    const float* __restrict__ W,
    const float* __restrict__ bias,
    float* __restrict__ hout)
{
    const int tid  = threadIdx.x;
    const int lane = tid & 31;
    const int wid  = tid >> 5;                 // 0..15
    const float4* __restrict__ hv = (const float4*)hin;

    // ---- load full W into smem (4096 float4 / 512 threads = 8 each) ----
#pragma unroll
    for (int i = 0; i < 8; i++) {
        int idx = tid + i * NTHR;              // float4 index into 128x128
        int k   = idx >> 5;
        int c4  = (idx & 31) * 4;
        *(float4*)&sm.Wf[k][c4] = __ldg((const float4*)&W[k * 128 + c4]);
    }
    __syncthreads();

    const int ty = tid >> 5;                   // 0..15
    const int tx = tid & 31;                   // 0..31
    const int rbase = ty * 4;                  // 0..60
    const int cbase = tx * 4;                  // 0..124
    const float4 bv = *(const float4*)&bias[cbase];

    for (int tile = blockIdx.x; tile * 64 < N_NODES; tile += NBLK) {
        const int row0 = tile * 64;

        // ---- Phase A: aggregate 64 nodes (one warp per node, 4 nodes/warp) ----
#pragma unroll
        for (int n = wid; n < 64; n += 16) {
            int node = row0 + n;
            float4 a = make_float4(0.f, 0.f, 0.f, 0.f);
            if (node < N_NODES) {
                a = hv[node * 32 + lane];
                int beg = g_rowstart[node];
                int end = g_rowstart[node + 1];
                for (int k = beg; k < end; k += 8) {
                    int kk = k + (lane & 7);
                    int myj = (kk < end) ? g_csr[kk] : -1;
#pragma unroll
                    for (int e = 0; e < 8; e++) {
                        int j = __shfl_sync(0xffffffffu, myj, e);
                        if (j >= 0) {
                            float4 v = hv[j * 32 + lane];
                            a.x += v.x; a.y += v.y; a.z += v.z; a.w += v.w;
                        }
                    }
                }
            }
            *(float4*)&sm.Xs[n][lane * 4] = a;
        }
        __syncthreads();

        // ---- Phase B: hout[row0:row0+64, :] = Xs @ Wf + b ----
        float acc[4][4];
#pragma unroll
        for (int r = 0; r < 4; r++)
#pragma unroll
            for (int c = 0; c < 4; c++) acc[r][c] = 0.f;

#pragma unroll 4
        for (int k = 0; k < 128; k += 4) {
            float4 xf[4];
#pragma unroll
            for (int r = 0; r < 4; r++)
                xf[r] = *(const float4*)&sm.Xs[rbase + r][k];   // warp-broadcast
            float4 w0 = *(const float4*)&sm.Wf[k + 0][cbase];
            float4 w1 = *(const float4*)&sm.Wf[k + 1][cbase];
            float4 w2 = *(const float4*)&sm.Wf[k + 2][cbase];
            float4 w3 = *(const float4*)&sm.Wf[k + 3][cbase];
#pragma unroll
            for (int r = 0; r < 4; r++) {
                acc[r][0] += xf[r].x * w0.x + xf[r].y * w1.x + xf[r].z * w2.x + xf[r].w * w3.x;
                acc[r][1] += xf[r].x * w0.y + xf[r].y * w1.y + xf[r].z * w2.y + xf[r].w * w3.y;
                acc[r][2] += xf[r].x * w0.z + xf[r].y * w1.z + xf[r].z * w2.z + xf[r].w * w3.z;
                acc[r][3] += xf[r].x * w0.w + xf[r].y * w1.w + xf[r].z * w2.w + xf[r].w * w3.w;
            }
        }

#pragma unroll
        for (int r = 0; r < 4; r++) {
            int row = row0 + rbase + r;
            if (row < N_NODES) {
                float4 o;
                o.x = acc[r][0] + bv.x; o.y = acc[r][1] + bv.y;
                o.z = acc[r][2] + bv.z; o.w = acc[r][3] + bv.w;
                *(float4*)&hout[(long)row * D + cbase] = o;
            }
        }
        __syncthreads();   // protect Xs before next tile's Phase A
    }
}

// ---------------------------------------------------------------------------
__global__ __launch_bounds__(NTHR) void gin_persistent_kernel(
    const float* __restrict__ h,
    const int*   __restrict__ ei,
    const float* __restrict__ W0, const float* __restrict__ b0,
    const float* __restrict__ W1, const float* __restrict__ b1,
    const float* __restrict__ W2, const float* __restrict__ b2,
    const float* __restrict__ W3, const float* __restrict__ b3,
    float* __restrict__ out)
{
    extern __shared__ char smem_raw[];
    SMem& sm = *reinterpret_cast<SMem*>(smem_raw);
    const int tid = threadIdx.x;
    unsigned sense = 0;

    // ---- Phase 1: count in-degrees (g_deg is 0 on entry) ----
    for (int e = blockIdx.x * NTHR + tid; e < N_EDGES; e += NBLK * NTHR)
        atomicAdd(&g_deg[ei[N_EDGES + e]], 1);
    grid_barrier(sense);                                   // b1

    // ---- Phase 2: exclusive scan (block 0 only), reset deg/cursor ----
    if (blockIdx.x == 0) {
        int* partial = (int*)sm.Xs;                        // 2 KB scratch
        const int CH = (N_NODES + NTHR - 1) / NTHR;        // 40
        const int base = tid * CH;

        int s = 0;
        for (int j = 0; j < CH; j++) {
            int idx = base + j;
            if (idx < N_NODES) s += g_deg[idx];
        }
        partial[tid] = s;
        __syncthreads();
        for (int off = 1; off < NTHR; off <<= 1) {
            int v = 0;
            if (tid >= off) v = partial[tid - off];
            __syncthreads();
            if (tid >= off) partial[tid] += v;
            __syncthreads();
        }
        int run = (tid > 0) ? partial[tid - 1] : 0;
        for (int j = 0; j < CH; j++) {
            int idx = base + j;
            if (idx < N_NODES) {
                g_rowstart[idx] = run;
                run += g_deg[idx];
                g_deg[idx]    = 0;     // reset for next replay
                g_cursor[idx] = 0;     // reset for fill phase
            }
        }
        if (tid == NTHR - 1) g_rowstart[N_NODES] = partial[NTHR - 1];
        __syncthreads();
    }
    grid_barrier(sense);                                   // b2

    // ---- Phase 3: fill CSR ----
    for (int e = blockIdx.x * NTHR + tid; e < N_EDGES; e += NBLK * NTHR) {
        int s = ei[e];
        int d = ei[N_EDGES + e];
        int pos = atomicAdd(&g_cursor[d], 1);
        g_csr[g_rowstart[d] + pos] = s;
    }
    grid_barrier(sense);                                   // b3

    // ---- Phases 4-7: the four GIN layers ----
    do_layer(sm, h,    W0, b0, g_h0);
    grid_barrier(sense);                                   // b4
    do_layer(sm, g_h0, W1, b1, g_h1);
    grid_barrier(sense);                                   // b5
    do_layer(sm, g_h1, W2, b2, g_h2);
    grid_barrier(sense);                                   // b6 (even -> sense ends 0)
    do_layer(sm, g_h2, W3, b3, out);
}

// ---------------------------------------------------------------------------
extern "C" void kernel_launch(void* const* d_in, const int* in_sizes, int n_in,
                              void* d_out, int out_size) {
    const float* h  = (const float*)d_in[0];
    const int*   ei = (const int*)d_in[1];

    // capture-safe config call (not an allocation, not stream work)
    cudaFuncSetAttribute(gin_persistent_kernel,
                         cudaFuncAttributeMaxDynamicSharedMemorySize,
                         (int)sizeof(SMem));

    gin_persistent_kernel<<<NBLK, NTHR, sizeof(SMem)>>>(
        h, ei,
        (const float*)d_in[2], (const float*)d_in[3],
        (const float*)d_in[4], (const float*)d_in[5],
        (const float*)d_in[6], (const float*)d_in[7],
        (const float*)d_in[8], (const float*)d_in[9],
        (float*)d_out);
}

// round 8
// speedup vs baseline: 17.1056x; 1.1433x over previous
#include <cuda_runtime.h>

#define N_NODES 20000
#define N_EDGES 640000
#define D 128
#define NBLK 148          // 1 block/SM -> co-residency guaranteed for grid barrier
#define NTHR 1024
#define TILE 128
#define NTILES ((N_NODES + TILE - 1) / TILE)   // 157

// ---- scratch (no allocations). .bss zero-init. All mutable globals return to
// a deterministic state each run (sense is read at kernel start, counters are
// reset by barrier completers), so graph replays are safe. ----
__device__ int      g_deg[N_NODES];
__device__ int      g_cursor[N_NODES];
__device__ int      g_rowstart[N_NODES + 1];
__device__ int      g_csr[N_EDGES];
__device__ float    g_h0[N_NODES * D];
__device__ float    g_h1[N_NODES * D];
__device__ float    g_h2[N_NODES * D];
__device__ unsigned g_bar_count;     // self-resetting
__device__ unsigned g_bar_sense;     // read at kernel start (parity-agnostic)
__device__ int      g_tile_ctr[4];   // per-layer ticket counters, reset at barriers

struct SMem {
    float Xs[TILE][128];   // 64 KB : aggregated rows for current tile
    float Wf[128][128];    // 64 KB : full W, resident for the whole layer
    int   ticket;
};

// sense-reversing grid barrier; all NBLK blocks co-resident (1/SM).
// Optional: completer resets *reset_ctr to 0 before releasing.
__device__ __forceinline__ void grid_barrier(unsigned& sense, int* reset_ctr) {
    __syncthreads();
    sense ^= 1u;
    if (threadIdx.x == 0) {
        __threadfence();
        unsigned arrived = atomicAdd(&g_bar_count, 1u);
        if (arrived == NBLK - 1) {
            g_bar_count = 0;
            if (reset_ctr) *reset_ctr = 0;
            __threadfence();
            atomicExch(&g_bar_sense, sense);
        } else {
            while (atomicAdd(&g_bar_sense, 0u) != sense) __nanosleep(64);
        }
    }
    __syncthreads();
}

// ---------------------------------------------------------------------------
// one fused layer with dynamic tile tickets. hin != hout.
__device__ __forceinline__ void do_layer(
    SMem& sm,
    const float* __restrict__ hin,
    const float* __restrict__ W,
    const float* __restrict__ bias,
    float* __restrict__ hout,
    int* tile_ctr)
{
    const int tid  = threadIdx.x;
    const int lane = tid & 31;
    const int wid  = tid >> 5;                 // 0..31
    const float4* __restrict__ hv = (const float4*)hin;

    // ---- load full W into smem (4096 float4 / 1024 threads = 4 each) ----
#pragma unroll
    for (int i = 0; i < 4; i++) {
        int idx = tid + i * NTHR;
        int k   = idx >> 5;
        int c4  = (idx & 31) * 4;
        *(float4*)&sm.Wf[k][c4] = __ldg((const float4*)&W[k * 128 + c4]);
    }

    const int rbase = (tid >> 5) * 4;          // 0..124 (warp-uniform)
    const int cbase = (tid & 31) * 4;          // 0..124
    const float4 bv = *(const float4*)&bias[cbase];

    for (;;) {
        if (tid == 0) sm.ticket = atomicAdd(tile_ctr, 1);
        __syncthreads();                       // also covers W load on iter 0
        const int tile = sm.ticket;
        if (tile >= NTILES) break;
        const int row0 = tile * TILE;

        // ---- Phase A: aggregate TILE nodes (one warp per node, 4/warp) ----
#pragma unroll
        for (int n = wid; n < TILE; n += 32) {
            int node = row0 + n;
            float4 a = make_float4(0.f, 0.f, 0.f, 0.f);
            if (node < N_NODES) {
                a = hv[node * 32 + lane];
                int beg = g_rowstart[node];
                int end = g_rowstart[node + 1];
                for (int k = beg; k < end; k += 8) {
                    int kk = k + (lane & 7);
                    int myj = (kk < end) ? g_csr[kk] : -1;
#pragma unroll
                    for (int e = 0; e < 8; e++) {
                        int j = __shfl_sync(0xffffffffu, myj, e);
                        if (j >= 0) {
                            float4 v = hv[j * 32 + lane];
                            a.x += v.x; a.y += v.y; a.z += v.z; a.w += v.w;
                        }
                    }
                }
            }
            *(float4*)&sm.Xs[n][lane * 4] = a;
        }
        __syncthreads();

        // ---- Phase B: hout[row0 : row0+TILE, :] = Xs @ Wf + b ----
        // 4x4 fragment/thread: X reads warp-broadcast (1 wf), W reads 512B
        // rows (4 wf) -> 2 B/FMA total, crossbar == FMA balance point.
        float acc[4][4];
#pragma unroll
        for (int r = 0; r < 4; r++)
#pragma unroll
            for (int c = 0; c < 4; c++) acc[r][c] = 0.f;

#pragma unroll 2
        for (int k = 0; k < 128; k += 4) {
            float4 xf[4];
#pragma unroll
            for (int r = 0; r < 4; r++)
                xf[r] = *(const float4*)&sm.Xs[rbase + r][k];
#pragma unroll
            for (int kk = 0; kk < 4; kk++) {
                float4 w = *(const float4*)&sm.Wf[k + kk][cbase];
#pragma unroll
                for (int r = 0; r < 4; r++) {
                    float xv = (kk == 0) ? xf[r].x : (kk == 1) ? xf[r].y
                             : (kk == 2) ? xf[r].z : xf[r].w;
                    acc[r][0] += xv * w.x;
                    acc[r][1] += xv * w.y;
                    acc[r][2] += xv * w.z;
                    acc[r][3] += xv * w.w;
                }
            }
        }

#pragma unroll
        for (int r = 0; r < 4; r++) {
            int row = row0 + rbase + r;
            if (row < N_NODES) {
                float4 o;
                o.x = acc[r][0] + bv.x; o.y = acc[r][1] + bv.y;
                o.z = acc[r][2] + bv.z; o.w = acc[r][3] + bv.w;
                *(float4*)&hout[(long)row * D + cbase] = o;
            }
        }
        // loop-top __syncthreads orders these Xs reads vs next Phase A writes
    }
}

// ---------------------------------------------------------------------------
__global__ __launch_bounds__(NTHR) void gin_persistent_kernel(
    const float* __restrict__ h,
    const int*   __restrict__ ei,
    const float* __restrict__ W0, const float* __restrict__ b0,
    const float* __restrict__ W1, const float* __restrict__ b1,
    const float* __restrict__ W2, const float* __restrict__ b2,
    const float* __restrict__ W3, const float* __restrict__ b3,
    float* __restrict__ out)
{
    extern __shared__ char smem_raw[];
    SMem& sm = *reinterpret_cast<SMem*>(smem_raw);
    const int tid = threadIdx.x;

    // parity-agnostic: start from whatever sense the previous replay left
    unsigned sense = *(volatile unsigned*)&g_bar_sense;

    // ---- Phase 1: count in-degrees (g_deg is 0 on entry) ----
    for (int e = blockIdx.x * NTHR + tid; e < N_EDGES; e += NBLK * NTHR)
        atomicAdd(&g_deg[ei[N_EDGES + e]], 1);
    grid_barrier(sense, nullptr);

    // ---- Phase 2: exclusive scan (block 0 only), reset deg/cursor ----
    if (blockIdx.x == 0) {
        int* partial = (int*)sm.Xs;                        // 4 KB scratch
        const int CH = (N_NODES + NTHR - 1) / NTHR;        // 20
        const int base = tid * CH;

        int s = 0;
        for (int j = 0; j < CH; j++) {
            int idx = base + j;
            if (idx < N_NODES) s += g_deg[idx];
        }
        partial[tid] = s;
        __syncthreads();
        for (int off = 1; off < NTHR; off <<= 1) {
            int v = 0;
            if (tid >= off) v = partial[tid - off];
            __syncthreads();
            if (tid >= off) partial[tid] += v;
            __syncthreads();
        }
        int run = (tid > 0) ? partial[tid - 1] : 0;
        for (int j = 0; j < CH; j++) {
            int idx = base + j;
            if (idx < N_NODES) {
                g_rowstart[idx] = run;
                run += g_deg[idx];
                g_deg[idx]    = 0;     // reset for next replay
                g_cursor[idx] = 0;     // reset for fill phase
            }
        }
        if (tid == NTHR - 1) g_rowstart[N_NODES] = partial[NTHR - 1];
        __syncthreads();
    }
    grid_barrier(sense, nullptr);

    // ---- Phase 3: fill CSR ----
    for (int e = blockIdx.x * NTHR + tid; e < N_EDGES; e += NBLK * NTHR) {
        int s = ei[e];
        int d = ei[N_EDGES + e];
        int pos = atomicAdd(&g_cursor[d], 1);
        g_csr[g_rowstart[d] + pos] = s;
    }
    grid_barrier(sense, nullptr);

    // ---- Phases 4-7: the four GIN layers (dynamic tiles per layer) ----
    do_layer(sm, h,    W0, b0, g_h0, &g_tile_ctr[0]);
    grid_barrier(sense, &g_tile_ctr[0]);
    do_layer(sm, g_h0, W1, b1, g_h1, &g_tile_ctr[1]);
    grid_barrier(sense, &g_tile_ctr[1]);
    do_layer(sm, g_h1, W2, b2, g_h2, &g_tile_ctr[2]);
    grid_barrier(sense, &g_tile_ctr[2]);
    do_layer(sm, g_h2, W3, b3, out,  &g_tile_ctr[3]);
    grid_barrier(sense, &g_tile_ctr[3]);   // resets last counter for replay
}

// ---------------------------------------------------------------------------
extern "C" void kernel_launch(void* const* d_in, const int* in_sizes, int n_in,
                              void* d_out, int out_size) {
    const float* h  = (const float*)d_in[0];
    const int*   ei = (const int*)d_in[1];

    cudaFuncSetAttribute(gin_persistent_kernel,
                         cudaFuncAttributeMaxDynamicSharedMemorySize,
                         (int)sizeof(SMem));

    gin_persistent_kernel<<<NBLK, NTHR, sizeof(SMem)>>>(
        h, ei,
        (const float*)d_in[2], (const float*)d_in[3],
        (const float*)d_in[4], (const float*)d_in[5],
        (const float*)d_in[6], (const float*)d_in[7],
        (const float*)d_in[8], (const float*)d_in[9],
        (float*)d_out);
}

// round 9
// speedup vs baseline: 23.4823x; 1.3728x over previous
#include <cuda_runtime.h>

#define N_NODES 20000
#define N_EDGES 640000
#define D 128
#define NBLK 148          // 1 block/SM -> co-residency guaranteed for grid barrier
#define NTHR 1024
#define WTICKETS 5000     // 4 nodes per warp-ticket; 5000*4 == N_NODES exactly

// ---- scratch (no allocations). .bss zero-init. All mutable globals return to
// a deterministic state each run (sense read at kernel start, counters reset
// by barrier completers), so graph replays are safe. ----
__device__ int      g_deg[N_NODES];
__device__ int      g_cursor[N_NODES];
__device__ int      g_rowstart[N_NODES + 1];
__device__ int      g_csr[N_EDGES];
__device__ float    g_h0[N_NODES * D];
__device__ float    g_h1[N_NODES * D];
__device__ float    g_h2[N_NODES * D];
__device__ unsigned g_bar_count;     // self-resetting
__device__ unsigned g_bar_sense;     // read at kernel start (parity-agnostic)
__device__ int      g_tile_ctr[4];   // per-layer ticket counters, reset at barriers

struct SMem {
    float Xs[32][4][128];  // 64 KB : per-warp private 4-row staging
    float Wf[128][128];    // 64 KB : full W, block-shared, resident per layer
};

// sense-reversing grid barrier; all NBLK blocks co-resident (1/SM).
__device__ __forceinline__ void grid_barrier(unsigned& sense, int* reset_ctr) {
    __syncthreads();
    sense ^= 1u;
    if (threadIdx.x == 0) {
        __threadfence();
        unsigned arrived = atomicAdd(&g_bar_count, 1u);
        if (arrived == NBLK - 1) {
            g_bar_count = 0;
            if (reset_ctr) *reset_ctr = 0;
            __threadfence();
            atomicExch(&g_bar_sense, sense);
        } else {
            while (atomicAdd(&g_bar_sense, 0u) != sense) __nanosleep(64);
        }
    }
    __syncthreads();
}

// ---------------------------------------------------------------------------
// one fused layer, warp-autonomous: each warp independently pulls 4-node
// tickets, gathers into its private smem slice, GEMMs against shared W.
// NO block-level sync inside the ticket loop.
__device__ __forceinline__ void do_layer(
    SMem& sm,
    const float* __restrict__ hin,
    const float* __restrict__ W,
    const float* __restrict__ bias,
    float* __restrict__ hout,
    int* ticket_ctr)
{
    const int tid  = threadIdx.x;
    const int lane = tid & 31;
    const int wid  = tid >> 5;                 // 0..31
    const float4* __restrict__ hv = (const float4*)hin;

    // ---- load full W into smem (4096 float4 / 1024 threads = 4 each) ----
#pragma unroll
    for (int i = 0; i < 4; i++) {
        int idx = tid + i * NTHR;
        int k   = idx >> 5;
        int c4  = (idx & 31) * 4;
        *(float4*)&sm.Wf[k][c4] = __ldg((const float4*)&W[k * 128 + c4]);
    }
    __syncthreads();                           // W ready for all warps

    float (*Xw)[128] = sm.Xs[wid];             // this warp's 4-row slice
    const int cb = lane * 4;                   // lane's 4 output columns
    const float4 bv = *(const float4*)&bias[cb];

    for (;;) {
        int t;
        if (lane == 0) t = atomicAdd(ticket_ctr, 1);
        t = __shfl_sync(0xffffffffu, t, 0);
        if (t >= WTICKETS) break;
        const int node0 = t * 4;

        // ---- gather 4 node rows (16 edges in flight per warp) ----
#pragma unroll
        for (int n = 0; n < 4; n++) {
            int node = node0 + n;
            float4 a = hv[node * 32 + lane];
            int beg = g_rowstart[node];
            int end = g_rowstart[node + 1];
            for (int k = beg; k < end; k += 16) {
                int kk = k + (lane & 15);
                int myj = (kk < end) ? g_csr[kk] : -1;
#pragma unroll
                for (int e = 0; e < 16; e++) {
                    int j = __shfl_sync(0xffffffffu, myj, e);
                    if (j >= 0) {
                        float4 v = hv[j * 32 + lane];
                        a.x += v.x; a.y += v.y; a.z += v.z; a.w += v.w;
                    }
                }
            }
            *(float4*)&Xw[n][lane * 4] = a;
        }
        __syncwarp();                          // publish Xw across lanes

        // ---- GEMM: hout[node0:node0+4, :] = Xw @ Wf + b ----
        float acc[4][4];
#pragma unroll
        for (int r = 0; r < 4; r++)
#pragma unroll
            for (int c = 0; c < 4; c++) acc[r][c] = 0.f;

#pragma unroll 2
        for (int k = 0; k < 128; k += 4) {
            float4 xf[4];
#pragma unroll
            for (int r = 0; r < 4; r++)
                xf[r] = *(const float4*)&Xw[r][k];     // warp-broadcast
#pragma unroll
            for (int kk = 0; kk < 4; kk++) {
                float4 w = *(const float4*)&sm.Wf[k + kk][cb];
#pragma unroll
                for (int r = 0; r < 4; r++) {
                    float xv = (kk == 0) ? xf[r].x : (kk == 1) ? xf[r].y
                             : (kk == 2) ? xf[r].z : xf[r].w;
                    acc[r][0] += xv * w.x;
                    acc[r][1] += xv * w.y;
                    acc[r][2] += xv * w.z;
                    acc[r][3] += xv * w.w;
                }
            }
        }

#pragma unroll
        for (int r = 0; r < 4; r++) {
            float4 o;
            o.x = acc[r][0] + bv.x; o.y = acc[r][1] + bv.y;
            o.z = acc[r][2] + bv.z; o.w = acc[r][3] + bv.w;
            *(float4*)&hout[(long)(node0 + r) * D + cb] = o;
        }
        __syncwarp();                          // Xw reads done before next gather
    }
}

// ---------------------------------------------------------------------------
__global__ __launch_bounds__(NTHR) void gin_persistent_kernel(
    const float* __restrict__ h,
    const int*   __restrict__ ei,
    const float* __restrict__ W0, const float* __restrict__ b0,
    const float* __restrict__ W1, const float* __restrict__ b1,
    const float* __restrict__ W2, const float* __restrict__ b2,
    const float* __restrict__ W3, const float* __restrict__ b3,
    float* __restrict__ out)
{
    extern __shared__ char smem_raw[];
    SMem& sm = *reinterpret_cast<SMem*>(smem_raw);
    const int tid = threadIdx.x;

    // parity-agnostic: start from whatever sense the previous replay left
    unsigned sense = *(volatile unsigned*)&g_bar_sense;

    // ---- Phase 1: count in-degrees (g_deg is 0 on entry) ----
    for (int e = blockIdx.x * NTHR + tid; e < N_EDGES; e += NBLK * NTHR)
        atomicAdd(&g_deg[ei[N_EDGES + e]], 1);
    grid_barrier(sense, nullptr);

    // ---- Phase 2: exclusive scan (block 0 only), reset deg/cursor ----
    if (blockIdx.x == 0) {
        int* partial = (int*)sm.Xs;                        // 4 KB scratch
        const int CH = (N_NODES + NTHR - 1) / NTHR;        // 20
        const int base = tid * CH;

        int s = 0;
        for (int j = 0; j < CH; j++) {
            int idx = base + j;
            if (idx < N_NODES) s += g_deg[idx];
        }
        partial[tid] = s;
        __syncthreads();
        for (int off = 1; off < NTHR; off <<= 1) {
            int v = 0;
            if (tid >= off) v = partial[tid - off];
            __syncthreads();
            if (tid >= off) partial[tid] += v;
            __syncthreads();
        }
        int run = (tid > 0) ? partial[tid - 1] : 0;
        for (int j = 0; j < CH; j++) {
            int idx = base + j;
            if (idx < N_NODES) {
                g_rowstart[idx] = run;
                run += g_deg[idx];
                g_deg[idx]    = 0;     // reset for next replay
                g_cursor[idx] = 0;     // reset for fill phase
            }
        }
        if (tid == NTHR - 1) g_rowstart[N_NODES] = partial[NTHR - 1];
        __syncthreads();
    }
    grid_barrier(sense, nullptr);

    // ---- Phase 3: fill CSR ----
    for (int e = blockIdx.x * NTHR + tid; e < N_EDGES; e += NBLK * NTHR) {
        int s = ei[e];
        int d = ei[N_EDGES + e];
        int pos = atomicAdd(&g_cursor[d], 1);
        g_csr[g_rowstart[d] + pos] = s;
    }
    grid_barrier(sense, nullptr);

    // ---- Phases 4-7: the four GIN layers (warp-level dynamic tickets) ----
    do_layer(sm, h,    W0, b0, g_h0, &g_tile_ctr[0]);
    grid_barrier(sense, &g_tile_ctr[0]);
    do_layer(sm, g_h0, W1, b1, g_h1, &g_tile_ctr[1]);
    grid_barrier(sense, &g_tile_ctr[1]);
    do_layer(sm, g_h1, W2, b2, g_h2, &g_tile_ctr[2]);
    grid_barrier(sense, &g_tile_ctr[2]);
    do_layer(sm, g_h2, W3, b3, out,  &g_tile_ctr[3]);
    grid_barrier(sense, &g_tile_ctr[3]);   // resets last counter for replay
}

// ---------------------------------------------------------------------------
extern "C" void kernel_launch(void* const* d_in, const int* in_sizes, int n_in,
                              void* d_out, int out_size) {
    const float* h  = (const float*)d_in[0];
    const int*   ei = (const int*)d_in[1];

    cudaFuncSetAttribute(gin_persistent_kernel,
                         cudaFuncAttributeMaxDynamicSharedMemorySize,
                         (int)sizeof(SMem));

    gin_persistent_kernel<<<NBLK, NTHR, sizeof(SMem)>>>(
        h, ei,
        (const float*)d_in[2], (const float*)d_in[3],
        (const float*)d_in[4], (const float*)d_in[5],
        (const float*)d_in[6], (const float*)d_in[7],
        (const float*)d_in[8], (const float*)d_in[9],
        (float*)d_out);
}